// round 14
// baseline (speedup 1.0000x reference)
#include <cuda_runtime.h>
#include <cuda_bf16.h>
#include <stdint.h>

#define NB 32
#define NT 96
#define NH 512
#define NV 10000
#define NG 2560   // gate rows: [ingate|outgate|cell|f1|f2] x 512

// ---------------- device scratch ----------------
__device__ __nv_bfloat16 g_logW[NV * NH];
__device__ __nv_bfloat16 g_Wx[NG * 1024];       // cols [x_a, x_f]
__device__ __nv_bfloat16 g_Wh[NG * 1024];       // cols [ha, hf]
__device__ float         g_att[NB * NH];
__device__ float         g_attb[NB * NG];
__device__ __nv_bfloat16 g_Xg[NB * NT * 1024];
__device__ float         g_Pre[NB * NT * NG];
__device__ __nv_bfloat16 g_Hin[640 * 1024];     // wave input [ha|hf], padded to 640 rows
__device__ float         g_Sout[640 * NG];      // wave GEMM output, padded
__device__ __nv_bfloat16 g_h[NB * NT * NH];
__device__ float         g_c[NB * NT * NH];

// ---------------- wavefront schedule (ternary tree, static) ----------------
__constant__ int c_wcnt[13] = {1,1,1,1,3,3,3,9,9,9,19,19,18};
__constant__ int c_wn[13][19] = {
    {0},
    {1}, {2}, {3},
    {4,7,10}, {5,8,11}, {6,9,12},
    {13,16,19,22,25,28,31,34,37},
    {14,17,20,23,26,29,32,35,38},
    {15,18,21,24,27,30,33,36,39},
    {40,43,46,49,52,55,58,61,64,67,70,73,76,79,82,85,88,91,94},
    {41,44,47,50,53,56,59,62,65,68,71,74,77,80,83,86,89,92,95},
    {42,45,48,51,54,57,60,63,66,69,72,75,78,81,84,87,90,93}
};
static const int h_wcnt[13]  = {1,1,1,1,3,3,3,9,9,9,19,19,18};
static const int h_mtile[13] = {1,1,1,1,2,2,2,5,5,5,10,10,9};  // ceil(32*cnt/64)

// ---------------- helpers ----------------
__device__ __forceinline__ uint32_t smem_u32(const void* p) {
    return (uint32_t)__cvta_generic_to_shared(p);
}
__device__ __forceinline__ void ldm_x4(uint32_t* r, uint32_t a) {
    asm volatile("ldmatrix.sync.aligned.m8n8.x4.shared.b16 {%0,%1,%2,%3}, [%4];"
                 : "=r"(r[0]), "=r"(r[1]), "=r"(r[2]), "=r"(r[3]) : "r"(a));
}
__device__ __forceinline__ void mma16816(float* d, const uint32_t* a, const uint32_t* b) {
    asm volatile("mma.sync.aligned.m16n8k16.row.col.f32.bf16.bf16.f32 "
                 "{%0,%1,%2,%3}, {%4,%5,%6,%7}, {%8,%9}, {%0,%1,%2,%3};"
                 : "+f"(d[0]), "+f"(d[1]), "+f"(d[2]), "+f"(d[3])
                 : "r"(a[0]), "r"(a[1]), "r"(a[2]), "r"(a[3]), "r"(b[0]), "r"(b[1]));
}
__device__ __forceinline__ float sigm(float x) { return 1.f / (1.f + __expf(-x)); }
__device__ __forceinline__ void cp16(uint32_t dst, const void* src) {
    asm volatile("cp.async.cg.shared.global [%0], [%1], 16;" :: "r"(dst), "l"(src));
}

// ---------- init: bf16 conversions + Wx/Wh assembly + non-cell attb biases ----------
__global__ void init_convert(const float* __restrict__ WH,
                             const float* __restrict__ WI, const float* __restrict__ Wf1,
                             const float* __restrict__ Wf2, const float* __restrict__ logW,
                             const float* __restrict__ bH, const float* __restrict__ b1,
                             const float* __restrict__ b2) {
    int st = gridDim.x * blockDim.x, t0 = blockIdx.x * blockDim.x + threadIdx.x;
    for (int i = t0; i < NV * NH; i += st) g_logW[i] = __float2bfloat16(logW[i]);
    for (int i = t0; i < NG * 1024; i += st) {
        int n = i >> 10, k = i & 1023;
        float vx = 0.f, vh = 0.f;
        if (n < 1024)      { vx = WH[n * 2048 + k]; vh = WH[n * 2048 + 1024 + k]; }
        else if (n < 1536) { int m = n - 1024; vx = WI[m * 2560 + k]; vh = WI[m * 2560 + 1024 + k]; }
        else if (n < 2048) { int m = n - 1536;
                             if (k < 512) { vx = Wf1[m * 1024 + k]; vh = Wf1[m * 1024 + 512 + k]; } }
        else               { int m = n - 2048;
                             if (k >= 512) { vx = Wf2[m * 1024 + k - 512]; vh = Wf2[m * 1024 + k]; } }
        g_Wx[i] = __float2bfloat16(vx);
        g_Wh[i] = __float2bfloat16(vh);
    }
    for (int i = t0; i < 640 * 1024; i += st) g_Hin[i] = __float2bfloat16(0.f);
    for (int i = t0; i < NB * NG; i += st) {
        int n = i % NG;
        if (n >= 1024 && n < 1536) continue;   // cell rows: attb_mid owns
        float v;
        if (n < 1024) v = bH[n];
        else if (n < 2048) v = b1[n - 1536];
        else v = b2[n - 2048];
        g_attb[i] = v;
    }
}

// ---------- att = fc_feats @ fc_W^T + fc_b (fp32) ----------
__global__ __launch_bounds__(256) void att_kernel(const float* __restrict__ x,
                                                  const float* __restrict__ W,
                                                  const float* __restrict__ bias) {
    int gw = (blockIdx.x * 256 + threadIdx.x) >> 5, lane = threadIdx.x & 31;
    int b = gw >> 9, j = gw & 511;
    const float4* xa = (const float4*)(x + b * 2048);
    const float4* wa = (const float4*)(W + j * 2048);
    float s = 0.f;
    for (int k = lane; k < 512; k += 32) {
        float4 u = xa[k], v = wa[k];
        s += u.x * v.x + u.y * v.y + u.z * v.z + u.w * v.w;
    }
#pragma unroll
    for (int o = 16; o; o >>= 1) s += __shfl_xor_sync(~0u, s, o);
    if (!lane) g_att[b * NH + j] = s + bias[j];
}

// ---------- attb_mid: cell rows = bI + att . W_I[:,2048:2560] ----------
__global__ __launch_bounds__(256) void attb_mid(const float* __restrict__ WI,
                                                const float* __restrict__ bI) {
    int gw = (blockIdx.x * 256 + threadIdx.x) >> 5, lane = threadIdx.x & 31;
    int b = gw >> 9, m = gw & 511;
    const float4* xa = (const float4*)(g_att + b * NH);
    const float4* wa = (const float4*)(WI + m * 2560 + 2048);
    float s = 0.f;
#pragma unroll
    for (int k = lane; k < 128; k += 32) {
        float4 u = xa[k], v = wa[k];
        s += u.x * v.x + u.y * v.y + u.z * v.z + u.w * v.w;
    }
#pragma unroll
    for (int o = 16; o; o >>= 1) s += __shfl_xor_sync(~0u, s, o);
    if (!lane) g_attb[b * NG + 1024 + m] = s + bI[m];
}

// ---------- xgather: Xg[b*96+t] = [x_a | x_f], gather+convert from fp32 embed ----------
__global__ __launch_bounds__(128) void xgather(const int* __restrict__ wi,
                                               const int* __restrict__ fi,
                                               const float* __restrict__ embed) {
    int t = blockIdx.x, b = blockIdx.y, tid = threadIdx.x;
    __nv_bfloat16* dst = g_Xg + (b * NT + t) * 1024;
    int half = tid >> 6, li = tid & 63;      // 64 threads per 512-wide half, 8 elems each
    bool zero;
    int widx = 0;
    if (half == 0) { zero = (t == 0); if (!zero) widx = wi[b * NT + fi[b * NT + t]]; }
    else           { zero = (t == 0) || (((t - 1) % 3) == 0); if (!zero) widx = wi[b * NT + t - 1]; }
    __nv_bfloat16 v[8];
    if (zero) {
#pragma unroll
        for (int i = 0; i < 8; i++) v[i] = __float2bfloat16(0.f);
    } else {
        const float4* src = (const float4*)(embed + widx * NH + li * 8);
        float4 f0 = src[0], f1 = src[1];
        v[0] = __float2bfloat16(f0.x); v[1] = __float2bfloat16(f0.y);
        v[2] = __float2bfloat16(f0.z); v[3] = __float2bfloat16(f0.w);
        v[4] = __float2bfloat16(f1.x); v[5] = __float2bfloat16(f1.y);
        v[6] = __float2bfloat16(f1.z); v[7] = __float2bfloat16(f1.w);
    }
    *(uint4*)(dst + half * 512 + li * 8) = *(uint4*)v;
}

// ---------- pre_gemm: Pre[3072][2560] = Xg @ Wx^T + attb[row/96] ----------
__global__ __launch_bounds__(256) void pre_gemm() {
    __shared__ __align__(16) __nv_bfloat16 As[64][72];
    __shared__ __align__(16) __nv_bfloat16 Bs[128][72];
    int bm = blockIdx.y, bn = blockIdx.x;            // 48 x 20
    int tid = threadIdx.x, lane = tid & 31, warp = tid >> 5;
    int arow = tid >> 3, acg = tid & 7;
    const uint4* a0p = (const uint4*)(g_Xg + (bm * 64 + arow) * 1024 + acg * 8);
    const uint4* a1p = (const uint4*)(g_Xg + (bm * 64 + arow + 32) * 1024 + acg * 8);
    const uint4* bp[4];
#pragma unroll
    for (int i = 0; i < 4; i++)
        bp[i] = (const uint4*)(g_Wx + (bn * 128 + arow + i * 32) * 1024 + acg * 8);
    uint4 ra0 = a0p[0], ra1 = a1p[0], rb[4];
#pragma unroll
    for (int i = 0; i < 4; i++) rb[i] = bp[i][0];
    int wm = warp >> 2, wn = warp & 3;
    uint32_t ab0 = smem_u32(&As[wm * 32 + (lane & 15)][(lane >> 4) * 8]);
    uint32_t ab1 = ab0 + 16 * 72 * 2;
    uint32_t bb0 = smem_u32(&Bs[wn * 32 + (lane & 15)][(lane >> 4) * 8]);
    uint32_t bb1 = bb0 + 16 * 72 * 2;
    float acc[2][2][2][4] = {};
#pragma unroll 1
    for (int kk = 0; kk < 16; kk++) {
        *(uint4*)&As[arow][acg * 8] = ra0;
        *(uint4*)&As[arow + 32][acg * 8] = ra1;
#pragma unroll
        for (int i = 0; i < 4; i++) *(uint4*)&Bs[arow + i * 32][acg * 8] = rb[i];
        __syncthreads();
        if (kk < 15) {
            ra0 = a0p[(kk + 1) * 8]; ra1 = a1p[(kk + 1) * 8];
#pragma unroll
            for (int i = 0; i < 4; i++) rb[i] = bp[i][(kk + 1) * 8];
        }
#pragma unroll
        for (int k16 = 0; k16 < 4; k16++) {
            uint32_t a0[4], a1[4], q0[4], q1[4];
            ldm_x4(a0, ab0 + k16 * 32); ldm_x4(a1, ab1 + k16 * 32);
            ldm_x4(q0, bb0 + k16 * 32); ldm_x4(q1, bb1 + k16 * 32);
            uint32_t b00[2] = {q0[0], q0[2]}, b01[2] = {q0[1], q0[3]};
            uint32_t b10[2] = {q1[0], q1[2]}, b11[2] = {q1[1], q1[3]};
            mma16816(acc[0][0][0], a0, b00); mma16816(acc[0][0][1], a0, b01);
            mma16816(acc[1][0][0], a1, b00); mma16816(acc[1][0][1], a1, b01);
            mma16816(acc[0][1][0], a0, b10); mma16816(acc[0][1][1], a0, b11);
            mma16816(acc[1][1][0], a1, b10); mma16816(acc[1][1][1], a1, b11);
        }
        __syncthreads();
    }
    int g = lane >> 2, tg = lane & 3;
#pragma unroll
    for (int mt = 0; mt < 2; mt++) {
        int row = bm * 64 + wm * 32 + mt * 16 + g;
#pragma unroll
        for (int nt = 0; nt < 2; nt++)
#pragma unroll
            for (int s = 0; s < 2; s++) {
                int col = bn * 128 + wn * 32 + nt * 16 + s * 8 + tg * 2;
                float* q = acc[mt][nt][s];
                float2 u0 = *(const float2*)(g_attb + (row / NT) * NG + col);
                float2 u1 = *(const float2*)(g_attb + ((row + 8) / NT) * NG + col);
                *(float2*)&g_Pre[row * NG + col]       = make_float2(q[0] + u0.x, q[1] + u0.y);
                *(float2*)&g_Pre[(row + 8) * NG + col] = make_float2(q[2] + u1.x, q[3] + u1.y);
            }
    }
}

// ---------- wave GEMM (M-batched): Sout[Mpad,2560] = Hin[Mpad,1024] @ Wh^T ----------
__global__ __launch_bounds__(256) void wave_gemm64() {
    __shared__ __align__(16) __nv_bfloat16 As[64][72];
    __shared__ __align__(16) __nv_bfloat16 Bs[128][72];
    int bm = blockIdx.y, bn = blockIdx.x;
    int tid = threadIdx.x, lane = tid & 31, warp = tid >> 5;
    int arow = tid >> 3, acg = tid & 7;
    const uint4* a0p = (const uint4*)(g_Hin + (bm * 64 + arow) * 1024 + acg * 8);
    const uint4* a1p = (const uint4*)(g_Hin + (bm * 64 + arow + 32) * 1024 + acg * 8);
    const uint4* bp[4];
#pragma unroll
    for (int i = 0; i < 4; i++)
        bp[i] = (const uint4*)(g_Wh + (bn * 128 + arow + i * 32) * 1024 + acg * 8);
    uint4 ra0 = a0p[0], ra1 = a1p[0], rb[4];
#pragma unroll
    for (int i = 0; i < 4; i++) rb[i] = bp[i][0];
    int wm = warp >> 2, wn = warp & 3;
    uint32_t ab0 = smem_u32(&As[wm * 32 + (lane & 15)][(lane >> 4) * 8]);
    uint32_t ab1 = ab0 + 16 * 72 * 2;
    uint32_t bb0 = smem_u32(&Bs[wn * 32 + (lane & 15)][(lane >> 4) * 8]);
    uint32_t bb1 = bb0 + 16 * 72 * 2;
    float acc[2][2][2][4] = {};
#pragma unroll 1
    for (int kk = 0; kk < 16; kk++) {
        *(uint4*)&As[arow][acg * 8] = ra0;
        *(uint4*)&As[arow + 32][acg * 8] = ra1;
#pragma unroll
        for (int i = 0; i < 4; i++) *(uint4*)&Bs[arow + i * 32][acg * 8] = rb[i];
        __syncthreads();
        if (kk < 15) {
            ra0 = a0p[(kk + 1) * 8]; ra1 = a1p[(kk + 1) * 8];
#pragma unroll
            for (int i = 0; i < 4; i++) rb[i] = bp[i][(kk + 1) * 8];
        }
#pragma unroll
        for (int k16 = 0; k16 < 4; k16++) {
            uint32_t a0[4], a1[4], q0[4], q1[4];
            ldm_x4(a0, ab0 + k16 * 32); ldm_x4(a1, ab1 + k16 * 32);
            ldm_x4(q0, bb0 + k16 * 32); ldm_x4(q1, bb1 + k16 * 32);
            uint32_t b00[2] = {q0[0], q0[2]}, b01[2] = {q0[1], q0[3]};
            uint32_t b10[2] = {q1[0], q1[2]}, b11[2] = {q1[1], q1[3]};
            mma16816(acc[0][0][0], a0, b00); mma16816(acc[0][0][1], a0, b01);
            mma16816(acc[1][0][0], a1, b00); mma16816(acc[1][0][1], a1, b01);
            mma16816(acc[0][1][0], a0, b10); mma16816(acc[0][1][1], a0, b11);
            mma16816(acc[1][1][0], a1, b10); mma16816(acc[1][1][1], a1, b11);
        }
        __syncthreads();
    }
    int g = lane >> 2, tg = lane & 3;
#pragma unroll
    for (int mt = 0; mt < 2; mt++) {
        int row = bm * 64 + wm * 32 + mt * 16 + g;
#pragma unroll
        for (int nt = 0; nt < 2; nt++)
#pragma unroll
            for (int s = 0; s < 2; s++) {
                int col = bn * 128 + wn * 32 + nt * 16 + s * 8 + tg * 2;
                float* q = acc[mt][nt][s];
                *(float2*)&g_Sout[row * NG + col]       = make_float2(q[0], q[1]);
                *(float2*)&g_Sout[(row + 8) * NG + col] = make_float2(q[2], q[3]);
            }
    }
}

// ---------- wave combine: gates -> h,c; gather Hin for next wave ----------
__global__ __launch_bounds__(128) void wave_combine(int w, const int* __restrict__ fi) {
    int idx = blockIdx.x * 128 + threadIdx.x;    // 16384 = 32b x 512j
    int b = idx >> 9, j = idx & 511;
    int cnt = c_wcnt[w];
    for (int s = 0; s < cnt; s++) {
        int t = c_wn[w][s];
        const float* S = g_Sout + (s * 32 + b) * NG;
        const float* P = g_Pre + (b * NT + t) * NG;
        float ig = sigm(S[j] + P[j]);
        float og = sigm(S[512 + j] + P[512 + j]);
        float cg = tanhf(S[1024 + j] + P[1024 + j]);
        float f1 = sigm(S[1536 + j] + P[1536 + j]);
        float f2 = sigm(S[2048 + j] + P[2048 + j]);
        float ca = (t > 0) ? g_c[(b * NT + fi[b * NT + t]) * NH + j] : 0.f;
        bool p0 = (t == 0) || ((t - 1) % 3) == 0;
        float cf = p0 ? 0.f : g_c[(b * NT + t - 1) * NH + j];
        float c = f1 * ca + f2 * cf + ig * cg;
        float h = og * tanhf(c);
        g_c[(b * NT + t) * NH + j] = c;
        g_h[(b * NT + t) * NH + j] = __float2bfloat16(h);
    }
    if (w < 12) {
        int cnt2 = c_wcnt[w + 1];
        __nv_bfloat16 z = __float2bfloat16(0.f);
        for (int s = 0; s < cnt2; s++) {
            int t2 = c_wn[w + 1][s];
            int fa = fi[b * NT + t2];
            __nv_bfloat16 ha = g_h[(b * NT + fa) * NH + j];
            bool p0 = ((t2 - 1) % 3) == 0;
            __nv_bfloat16 hf = p0 ? z : g_h[(b * NT + t2 - 1) * NH + j];
            g_Hin[(s * 32 + b) * 1024 + j] = ha;
            g_Hin[(s * 32 + b) * 1024 + 512 + j] = hf;
        }
    }
}

// ---------- logits: out[3072,10000] = h @ logW^T + b ----------
// 64x128 tile, 3-stage cp.async pipeline, K-chunk 32 (16 iters).
__global__ __launch_bounds__(256) void logits_gemm(const float* __restrict__ lb,
                                                   float* __restrict__ out) {
    __shared__ __align__(16) __nv_bfloat16 As[3][64][40];
    __shared__ __align__(16) __nv_bfloat16 Bs[3][128][40];
    int bm = blockIdx.y, bn = blockIdx.x;
    int tid = threadIdx.x, lane = tid & 31, warp = tid >> 5;
    int wm = warp >> 2, wn = warp & 3;

    // A loader: 4 thr/row, 1x16B each -> 64 rows x 32 cols
    int arow = tid >> 2, ac = tid & 3;
    const __nv_bfloat16* apt = g_h + (size_t)(bm * 64 + arow) * NH + ac * 8;
    uint32_t aDst = smem_u32(&As[0][arow][ac * 8]);
    // B loader: 2 thr-groups x 128 rows, 2x16B each -> 128 rows x 32 cols
    int brow = tid & 127, bhalf = tid >> 7;
    int bglob = bn * 128 + brow;
    const __nv_bfloat16* bpt = g_logW + (size_t)(bglob < NV ? bglob : 0) * NH + bhalf * 16;
    uint32_t bDst = smem_u32(&Bs[0][brow][bhalf * 16]);
    const int ASTG = 64 * 40 * 2, BSTG = 128 * 40 * 2;

    uint32_t ab0 = smem_u32(&As[0][wm * 32 + (lane & 15)][(lane >> 4) * 8]);
    uint32_t ab1 = ab0 + 16 * 40 * 2;
    uint32_t bb0 = smem_u32(&Bs[0][wn * 32 + (lane & 15)][(lane >> 4) * 8]);
    uint32_t bb1 = bb0 + 16 * 40 * 2;

    // prologue: stages 0,1
#pragma unroll
    for (int pk = 0; pk < 2; pk++) {
        cp16(aDst + pk * ASTG, apt + pk * 32);
        cp16(bDst + pk * BSTG, bpt + pk * 32);
        cp16(bDst + pk * BSTG + 16, bpt + pk * 32 + 8);
        asm volatile("cp.async.commit_group;");
    }

    float acc[2][2][2][4] = {};
#pragma unroll 1
    for (int kk = 0; kk < 16; kk++) {
        if (kk >= 14) asm volatile("cp.async.wait_group 0;");
        else          asm volatile("cp.async.wait_group 1;");
        __syncthreads();
        if (kk + 2 < 16) {
            int st2 = (kk + 2) % 3;
            cp16(aDst + st2 * ASTG, apt + (kk + 2) * 32);
            cp16(bDst + st2 * BSTG, bpt + (kk + 2) * 32);
            cp16(bDst + st2 * BSTG + 16, bpt + (kk + 2) * 32 + 8);
            asm volatile("cp.async.commit_group;");
        }
        int st = kk % 3;
        uint32_t a0b = ab0 + st * ASTG, a1b = ab1 + st * ASTG;
        uint32_t b0b = bb0 + st * BSTG, b1b = bb1 + st * BSTG;
#pragma unroll
        for (int k16 = 0; k16 < 2; k16++) {
            uint32_t a0[4], a1[4], q0[4], q1[4];
            ldm_x4(a0, a0b + k16 * 32); ldm_x4(a1, a1b + k16 * 32);
            ldm_x4(q0, b0b + k16 * 32); ldm_x4(q1, b1b + k16 * 32);
            uint32_t b00[2] = {q0[0], q0[2]}, b01[2] = {q0[1], q0[3]};
            uint32_t b10[2] = {q1[0], q1[2]}, b11[2] = {q1[1], q1[3]};
            mma16816(acc[0][0][0], a0, b00); mma16816(acc[0][0][1], a0, b01);
            mma16816(acc[1][0][0], a1, b00); mma16816(acc[1][0][1], a1, b01);
            mma16816(acc[0][1][0], a0, b10); mma16816(acc[0][1][1], a0, b11);
            mma16816(acc[1][1][0], a1, b10); mma16816(acc[1][1][1], a1, b11);
        }
        __syncthreads();
    }
    int g = lane >> 2, tg = lane & 3;
#pragma unroll
    for (int mt = 0; mt < 2; mt++) {
        int row = bm * 64 + wm * 32 + mt * 16 + g;
#pragma unroll
        for (int nt = 0; nt < 2; nt++)
#pragma unroll
            for (int s = 0; s < 2; s++) {
                int col = bn * 128 + wn * 32 + nt * 16 + s * 8 + tg * 2;
                if (col < NV) {
                    float2 bbv = *(const float2*)(lb + col);
                    float* q = acc[mt][nt][s];
                    *(float2*)&out[row * NV + col]       = make_float2(q[0] + bbv.x, q[1] + bbv.y);
                    *(float2*)&out[(row + 8) * NV + col] = make_float2(q[2] + bbv.x, q[3] + bbv.y);
                }
            }
    }
}

// ---------- in-place log_softmax, one block per row ----------
__global__ __launch_bounds__(256) void logsoftmax_kernel(float* __restrict__ out) {
    __shared__ __align__(16) float buf[NV];
    __shared__ float red[10];
    float* p = out + (size_t)blockIdx.x * NV;
    int tid = threadIdx.x, lane = tid & 31, wid = tid >> 5;
    const float4* p4 = (const float4*)p;
    float4* b4 = (float4*)buf;
    float mx = -1e30f;
    for (int i = tid; i < NV / 4; i += 256) {
        float4 v = p4[i]; b4[i] = v;
        mx = fmaxf(fmaxf(mx, v.x), fmaxf(v.y, fmaxf(v.z, v.w)));
    }
#pragma unroll
    for (int o = 16; o; o >>= 1) mx = fmaxf(mx, __shfl_xor_sync(~0u, mx, o));
    if (!lane) red[wid] = mx;
    __syncthreads();
    if (tid == 0) {
        float m = red[0];
        for (int wq = 1; wq < 8; wq++) m = fmaxf(m, red[wq]);
        red[8] = m;
    }
    __syncthreads();
    mx = red[8];
    float s = 0.f;
    for (int i = tid; i < NV / 4; i += 256) {
        float4 v = b4[i];
        s += __expf(v.x - mx) + __expf(v.y - mx) + __expf(v.z - mx) + __expf(v.w - mx);
    }
#pragma unroll
    for (int o = 16; o; o >>= 1) s += __shfl_xor_sync(~0u, s, o);
    if (!lane) red[wid] = s;
    __syncthreads();
    if (tid == 0) {
        float tt = 0.f;
        for (int wq = 0; wq < 8; wq++) tt += red[wq];
        red[9] = mx + logf(tt);
    }
    __syncthreads();
    float lse = red[9];
    for (int i = tid; i < NV / 4; i += 256) {
        float4 v = b4[i];
        ((float4*)p)[i] = make_float4(v.x - lse, v.y - lse, v.z - lse, v.w - lse);
    }
}

extern "C" void kernel_launch(void* const* d_in, const int* in_sizes, int n_in,
                              void* d_out, int out_size) {
    const int*   wi    = (const int*)d_in[0];
    const int*   fi    = (const int*)d_in[1];
    const float* feats = (const float*)d_in[2];
    const float* embed = (const float*)d_in[3];
    const float* fcW   = (const float*)d_in[4];
    const float* fcb   = (const float*)d_in[5];
    const float* Wf1   = (const float*)d_in[6];
    const float* bf1   = (const float*)d_in[7];
    const float* Wf2   = (const float*)d_in[8];
    const float* bf2   = (const float*)d_in[9];
    const float* WH    = (const float*)d_in[10];
    const float* bH    = (const float*)d_in[11];
    const float* WI    = (const float*)d_in[12];
    const float* bI    = (const float*)d_in[13];
    const float* logW  = (const float*)d_in[14];
    const float* logb  = (const float*)d_in[15];
    float* out = (float*)d_out;

    init_convert<<<4096, 256>>>(WH, WI, Wf1, Wf2, logW, bH, bf1, bf2);
    att_kernel<<<2048, 256>>>(feats, fcW, fcb);
    attb_mid<<<2048, 256>>>(WI, bI);
    xgather<<<dim3(NT, NB), 128>>>(wi, fi, embed);
    pre_gemm<<<dim3(20, 48), 256>>>();
    for (int w = 0; w < 13; w++) {
        wave_gemm64<<<dim3(20, h_mtile[w]), 256>>>();
        wave_combine<<<128, 128>>>(w, fi);
    }
    logits_gemm<<<dim3(79, 48), 256>>>(logb, out);
    logsoftmax_kernel<<<NB * NT, 256>>>(out);
}

// round 15
// speedup vs baseline: 1.0905x; 1.0905x over previous
#include <cuda_runtime.h>
#include <cuda_bf16.h>
#include <stdint.h>

#define NB 32
#define NT 96
#define NH 512
#define NV 10000
#define NG 2560   // gate rows: [ingate|outgate|cell|f1|f2] x 512

// ---------------- device scratch ----------------
__device__ __nv_bfloat16 g_logW[NV * NH];
__device__ __nv_bfloat16 g_Wx[NG * 1024];       // cols [x_a, x_f]
__device__ __nv_bfloat16 g_Wh[NG * 1024];       // cols [ha, hf]
__device__ float         g_att[NB * NH];
__device__ float         g_attb[NB * NG];
__device__ __nv_bfloat16 g_Xg[NB * NT * 1024];
__device__ float         g_Pre[NB * NT * NG];
__device__ __nv_bfloat16 g_Hin[640 * 1024];     // wave input [ha|hf], padded to 640 rows
__device__ float         g_Sout[640 * NG];      // wave GEMM output, padded
__device__ __nv_bfloat16 g_h[NB * NT * NH];
__device__ float         g_c[NB * NT * NH];

// ---------------- wavefront schedule (ternary tree, static) ----------------
__constant__ int c_wcnt[13] = {1,1,1,1,3,3,3,9,9,9,19,19,18};
__constant__ int c_wn[13][19] = {
    {0},
    {1}, {2}, {3},
    {4,7,10}, {5,8,11}, {6,9,12},
    {13,16,19,22,25,28,31,34,37},
    {14,17,20,23,26,29,32,35,38},
    {15,18,21,24,27,30,33,36,39},
    {40,43,46,49,52,55,58,61,64,67,70,73,76,79,82,85,88,91,94},
    {41,44,47,50,53,56,59,62,65,68,71,74,77,80,83,86,89,92,95},
    {42,45,48,51,54,57,60,63,66,69,72,75,78,81,84,87,90,93}
};
static const int h_wcnt[13]  = {1,1,1,1,3,3,3,9,9,9,19,19,18};
static const int h_mtile[13] = {1,1,1,1,2,2,2,5,5,5,10,10,9};  // ceil(32*cnt/64)

// ---------------- helpers ----------------
__device__ __forceinline__ uint32_t smem_u32(const void* p) {
    return (uint32_t)__cvta_generic_to_shared(p);
}
__device__ __forceinline__ void ldm_x4(uint32_t* r, uint32_t a) {
    asm volatile("ldmatrix.sync.aligned.m8n8.x4.shared.b16 {%0,%1,%2,%3}, [%4];"
                 : "=r"(r[0]), "=r"(r[1]), "=r"(r[2]), "=r"(r[3]) : "r"(a));
}
__device__ __forceinline__ void mma16816(float* d, const uint32_t* a, const uint32_t* b) {
    asm volatile("mma.sync.aligned.m16n8k16.row.col.f32.bf16.bf16.f32 "
                 "{%0,%1,%2,%3}, {%4,%5,%6,%7}, {%8,%9}, {%0,%1,%2,%3};"
                 : "+f"(d[0]), "+f"(d[1]), "+f"(d[2]), "+f"(d[3])
                 : "r"(a[0]), "r"(a[1]), "r"(a[2]), "r"(a[3]), "r"(b[0]), "r"(b[1]));
}
__device__ __forceinline__ float sigm(float x) { return 1.f / (1.f + __expf(-x)); }

// ---------- init: bf16 conversions + Wx/Wh assembly + non-cell attb biases ----------
__global__ void init_convert(const float* __restrict__ WH,
                             const float* __restrict__ WI, const float* __restrict__ Wf1,
                             const float* __restrict__ Wf2, const float* __restrict__ logW,
                             const float* __restrict__ bH, const float* __restrict__ b1,
                             const float* __restrict__ b2) {
    int st = gridDim.x * blockDim.x, t0 = blockIdx.x * blockDim.x + threadIdx.x;
    for (int i = t0; i < NV * NH; i += st) g_logW[i] = __float2bfloat16(logW[i]);
    for (int i = t0; i < NG * 1024; i += st) {
        int n = i >> 10, k = i & 1023;
        float vx = 0.f, vh = 0.f;
        if (n < 1024)      { vx = WH[n * 2048 + k]; vh = WH[n * 2048 + 1024 + k]; }
        else if (n < 1536) { int m = n - 1024; vx = WI[m * 2560 + k]; vh = WI[m * 2560 + 1024 + k]; }
        else if (n < 2048) { int m = n - 1536;
                             if (k < 512) { vx = Wf1[m * 1024 + k]; vh = Wf1[m * 1024 + 512 + k]; } }
        else               { int m = n - 2048;
                             if (k >= 512) { vx = Wf2[m * 1024 + k - 512]; vh = Wf2[m * 1024 + k]; } }
        g_Wx[i] = __float2bfloat16(vx);
        g_Wh[i] = __float2bfloat16(vh);
    }
    for (int i = t0; i < 640 * 1024; i += st) g_Hin[i] = __float2bfloat16(0.f);
    for (int i = t0; i < NB * NG; i += st) {
        int n = i % NG;
        if (n >= 1024 && n < 1536) continue;   // cell rows: attb_mid owns
        float v;
        if (n < 1024) v = bH[n];
        else if (n < 2048) v = b1[n - 1536];
        else v = b2[n - 2048];
        g_attb[i] = v;
    }
}

// ---------- att = fc_feats @ fc_W^T + fc_b (fp32) ----------
__global__ __launch_bounds__(256) void att_kernel(const float* __restrict__ x,
                                                  const float* __restrict__ W,
                                                  const float* __restrict__ bias) {
    int gw = (blockIdx.x * 256 + threadIdx.x) >> 5, lane = threadIdx.x & 31;
    int b = gw >> 9, j = gw & 511;
    const float4* xa = (const float4*)(x + b * 2048);
    const float4* wa = (const float4*)(W + j * 2048);
    float s = 0.f;
    for (int k = lane; k < 512; k += 32) {
        float4 u = xa[k], v = wa[k];
        s += u.x * v.x + u.y * v.y + u.z * v.z + u.w * v.w;
    }
#pragma unroll
    for (int o = 16; o; o >>= 1) s += __shfl_xor_sync(~0u, s, o);
    if (!lane) g_att[b * NH + j] = s + bias[j];
}

// ---------- attb_mid: cell rows = bI + att . W_I[:,2048:2560] ----------
__global__ __launch_bounds__(256) void attb_mid(const float* __restrict__ WI,
                                                const float* __restrict__ bI) {
    int gw = (blockIdx.x * 256 + threadIdx.x) >> 5, lane = threadIdx.x & 31;
    int b = gw >> 9, m = gw & 511;
    const float4* xa = (const float4*)(g_att + b * NH);
    const float4* wa = (const float4*)(WI + m * 2560 + 2048);
    float s = 0.f;
#pragma unroll
    for (int k = lane; k < 128; k += 32) {
        float4 u = xa[k], v = wa[k];
        s += u.x * v.x + u.y * v.y + u.z * v.z + u.w * v.w;
    }
#pragma unroll
    for (int o = 16; o; o >>= 1) s += __shfl_xor_sync(~0u, s, o);
    if (!lane) g_attb[b * NG + 1024 + m] = s + bI[m];
}

// ---------- xgather: Xg[b*96+t] = [x_a | x_f], gather+convert from fp32 embed ----------
__global__ __launch_bounds__(128) void xgather(const int* __restrict__ wi,
                                               const int* __restrict__ fi,
                                               const float* __restrict__ embed) {
    int t = blockIdx.x, b = blockIdx.y, tid = threadIdx.x;
    __nv_bfloat16* dst = g_Xg + (b * NT + t) * 1024;
    int half = tid >> 6, li = tid & 63;      // 64 threads per 512-wide half, 8 elems each
    bool zero;
    int widx = 0;
    if (half == 0) { zero = (t == 0); if (!zero) widx = wi[b * NT + fi[b * NT + t]]; }
    else           { zero = (t == 0) || (((t - 1) % 3) == 0); if (!zero) widx = wi[b * NT + t - 1]; }
    __nv_bfloat16 v[8];
    if (zero) {
#pragma unroll
        for (int i = 0; i < 8; i++) v[i] = __float2bfloat16(0.f);
    } else {
        const float4* src = (const float4*)(embed + widx * NH + li * 8);
        float4 f0 = src[0], f1 = src[1];
        v[0] = __float2bfloat16(f0.x); v[1] = __float2bfloat16(f0.y);
        v[2] = __float2bfloat16(f0.z); v[3] = __float2bfloat16(f0.w);
        v[4] = __float2bfloat16(f1.x); v[5] = __float2bfloat16(f1.y);
        v[6] = __float2bfloat16(f1.z); v[7] = __float2bfloat16(f1.w);
    }
    *(uint4*)(dst + half * 512 + li * 8) = *(uint4*)v;
}

// ---------- pre_gemm: Pre[3072][2560] = Xg @ Wx^T + attb[row/96] ----------
__global__ __launch_bounds__(256) void pre_gemm() {
    __shared__ __align__(16) __nv_bfloat16 As[64][72];
    __shared__ __align__(16) __nv_bfloat16 Bs[128][72];
    int bm = blockIdx.y, bn = blockIdx.x;            // 48 x 20
    int tid = threadIdx.x, lane = tid & 31, warp = tid >> 5;
    int arow = tid >> 3, acg = tid & 7;
    const uint4* a0p = (const uint4*)(g_Xg + (bm * 64 + arow) * 1024 + acg * 8);
    const uint4* a1p = (const uint4*)(g_Xg + (bm * 64 + arow + 32) * 1024 + acg * 8);
    const uint4* bp[4];
#pragma unroll
    for (int i = 0; i < 4; i++)
        bp[i] = (const uint4*)(g_Wx + (bn * 128 + arow + i * 32) * 1024 + acg * 8);
    uint4 ra0 = a0p[0], ra1 = a1p[0], rb[4];
#pragma unroll
    for (int i = 0; i < 4; i++) rb[i] = bp[i][0];
    int wm = warp >> 2, wn = warp & 3;
    uint32_t ab0 = smem_u32(&As[wm * 32 + (lane & 15)][(lane >> 4) * 8]);
    uint32_t ab1 = ab0 + 16 * 72 * 2;
    uint32_t bb0 = smem_u32(&Bs[wn * 32 + (lane & 15)][(lane >> 4) * 8]);
    uint32_t bb1 = bb0 + 16 * 72 * 2;
    float acc[2][2][2][4] = {};
#pragma unroll 1
    for (int kk = 0; kk < 16; kk++) {
        *(uint4*)&As[arow][acg * 8] = ra0;
        *(uint4*)&As[arow + 32][acg * 8] = ra1;
#pragma unroll
        for (int i = 0; i < 4; i++) *(uint4*)&Bs[arow + i * 32][acg * 8] = rb[i];
        __syncthreads();
        if (kk < 15) {
            ra0 = a0p[(kk + 1) * 8]; ra1 = a1p[(kk + 1) * 8];
#pragma unroll
            for (int i = 0; i < 4; i++) rb[i] = bp[i][(kk + 1) * 8];
        }
#pragma unroll
        for (int k16 = 0; k16 < 4; k16++) {
            uint32_t a0[4], a1[4], q0[4], q1[4];
            ldm_x4(a0, ab0 + k16 * 32); ldm_x4(a1, ab1 + k16 * 32);
            ldm_x4(q0, bb0 + k16 * 32); ldm_x4(q1, bb1 + k16 * 32);
            uint32_t b00[2] = {q0[0], q0[2]}, b01[2] = {q0[1], q0[3]};
            uint32_t b10[2] = {q1[0], q1[2]}, b11[2] = {q1[1], q1[3]};
            mma16816(acc[0][0][0], a0, b00); mma16816(acc[0][0][1], a0, b01);
            mma16816(acc[1][0][0], a1, b00); mma16816(acc[1][0][1], a1, b01);
            mma16816(acc[0][1][0], a0, b10); mma16816(acc[0][1][1], a0, b11);
            mma16816(acc[1][1][0], a1, b10); mma16816(acc[1][1][1], a1, b11);
        }
        __syncthreads();
    }
    int g = lane >> 2, tg = lane & 3;
#pragma unroll
    for (int mt = 0; mt < 2; mt++) {
        int row = bm * 64 + wm * 32 + mt * 16 + g;
#pragma unroll
        for (int nt = 0; nt < 2; nt++)
#pragma unroll
            for (int s = 0; s < 2; s++) {
                int col = bn * 128 + wn * 32 + nt * 16 + s * 8 + tg * 2;
                float* q = acc[mt][nt][s];
                float2 u0 = *(const float2*)(g_attb + (row / NT) * NG + col);
                float2 u1 = *(const float2*)(g_attb + ((row + 8) / NT) * NG + col);
                *(float2*)&g_Pre[row * NG + col]       = make_float2(q[0] + u0.x, q[1] + u0.y);
                *(float2*)&g_Pre[(row + 8) * NG + col] = make_float2(q[2] + u1.x, q[3] + u1.y);
            }
    }
}

// ---------- wave GEMM (M-batched): Sout[Mpad,2560] = Hin[Mpad,1024] @ Wh^T ----------
__global__ __launch_bounds__(256) void wave_gemm64() {
    __shared__ __align__(16) __nv_bfloat16 As[64][72];
    __shared__ __align__(16) __nv_bfloat16 Bs[128][72];
    int bm = blockIdx.y, bn = blockIdx.x;
    int tid = threadIdx.x, lane = tid & 31, warp = tid >> 5;
    int arow = tid >> 3, acg = tid & 7;
    const uint4* a0p = (const uint4*)(g_Hin + (bm * 64 + arow) * 1024 + acg * 8);
    const uint4* a1p = (const uint4*)(g_Hin + (bm * 64 + arow + 32) * 1024 + acg * 8);
    const uint4* bp[4];
#pragma unroll
    for (int i = 0; i < 4; i++)
        bp[i] = (const uint4*)(g_Wh + (bn * 128 + arow + i * 32) * 1024 + acg * 8);
    uint4 ra0 = a0p[0], ra1 = a1p[0], rb[4];
#pragma unroll
    for (int i = 0; i < 4; i++) rb[i] = bp[i][0];
    int wm = warp >> 2, wn = warp & 3;
    uint32_t ab0 = smem_u32(&As[wm * 32 + (lane & 15)][(lane >> 4) * 8]);
    uint32_t ab1 = ab0 + 16 * 72 * 2;
    uint32_t bb0 = smem_u32(&Bs[wn * 32 + (lane & 15)][(lane >> 4) * 8]);
    uint32_t bb1 = bb0 + 16 * 72 * 2;
    float acc[2][2][2][4] = {};
#pragma unroll 1
    for (int kk = 0; kk < 16; kk++) {
        *(uint4*)&As[arow][acg * 8] = ra0;
        *(uint4*)&As[arow + 32][acg * 8] = ra1;
#pragma unroll
        for (int i = 0; i < 4; i++) *(uint4*)&Bs[arow + i * 32][acg * 8] = rb[i];
        __syncthreads();
        if (kk < 15) {
            ra0 = a0p[(kk + 1) * 8]; ra1 = a1p[(kk + 1) * 8];
#pragma unroll
            for (int i = 0; i < 4; i++) rb[i] = bp[i][(kk + 1) * 8];
        }
#pragma unroll
        for (int k16 = 0; k16 < 4; k16++) {
            uint32_t a0[4], a1[4], q0[4], q1[4];
            ldm_x4(a0, ab0 + k16 * 32); ldm_x4(a1, ab1 + k16 * 32);
            ldm_x4(q0, bb0 + k16 * 32); ldm_x4(q1, bb1 + k16 * 32);
            uint32_t b00[2] = {q0[0], q0[2]}, b01[2] = {q0[1], q0[3]};
            uint32_t b10[2] = {q1[0], q1[2]}, b11[2] = {q1[1], q1[3]};
            mma16816(acc[0][0][0], a0, b00); mma16816(acc[0][0][1], a0, b01);
            mma16816(acc[1][0][0], a1, b00); mma16816(acc[1][0][1], a1, b01);
            mma16816(acc[0][1][0], a0, b10); mma16816(acc[0][1][1], a0, b11);
            mma16816(acc[1][1][0], a1, b10); mma16816(acc[1][1][1], a1, b11);
        }
        __syncthreads();
    }
    int g = lane >> 2, tg = lane & 3;
#pragma unroll
    for (int mt = 0; mt < 2; mt++) {
        int row = bm * 64 + wm * 32 + mt * 16 + g;
#pragma unroll
        for (int nt = 0; nt < 2; nt++)
#pragma unroll
            for (int s = 0; s < 2; s++) {
                int col = bn * 128 + wn * 32 + nt * 16 + s * 8 + tg * 2;
                float* q = acc[mt][nt][s];
                *(float2*)&g_Sout[row * NG + col]       = make_float2(q[0], q[1]);
                *(float2*)&g_Sout[(row + 8) * NG + col] = make_float2(q[2], q[3]);
            }
    }
}

// ---------- wave combine: gates -> h,c; gather Hin for next wave ----------
__global__ __launch_bounds__(128) void wave_combine(int w, const int* __restrict__ fi) {
    int idx = blockIdx.x * 128 + threadIdx.x;    // 16384 = 32b x 512j
    int b = idx >> 9, j = idx & 511;
    int cnt = c_wcnt[w];
    for (int s = 0; s < cnt; s++) {
        int t = c_wn[w][s];
        const float* S = g_Sout + (s * 32 + b) * NG;
        const float* P = g_Pre + (b * NT + t) * NG;
        float ig = sigm(S[j] + P[j]);
        float og = sigm(S[512 + j] + P[512 + j]);
        float cg = tanhf(S[1024 + j] + P[1024 + j]);
        float f1 = sigm(S[1536 + j] + P[1536 + j]);
        float f2 = sigm(S[2048 + j] + P[2048 + j]);
        float ca = (t > 0) ? g_c[(b * NT + fi[b * NT + t]) * NH + j] : 0.f;
        bool p0 = (t == 0) || ((t - 1) % 3) == 0;
        float cf = p0 ? 0.f : g_c[(b * NT + t - 1) * NH + j];
        float c = f1 * ca + f2 * cf + ig * cg;
        float h = og * tanhf(c);
        g_c[(b * NT + t) * NH + j] = c;
        g_h[(b * NT + t) * NH + j] = __float2bfloat16(h);
    }
    if (w < 12) {
        int cnt2 = c_wcnt[w + 1];
        __nv_bfloat16 z = __float2bfloat16(0.f);
        for (int s = 0; s < cnt2; s++) {
            int t2 = c_wn[w + 1][s];
            int fa = fi[b * NT + t2];
            __nv_bfloat16 ha = g_h[(b * NT + fa) * NH + j];
            bool p0 = ((t2 - 1) % 3) == 0;
            __nv_bfloat16 hf = p0 ? z : g_h[(b * NT + t2 - 1) * NH + j];
            g_Hin[(s * 32 + b) * 1024 + j] = ha;
            g_Hin[(s * 32 + b) * 1024 + 512 + j] = hf;
        }
    }
}

// ---------- logits: out[3072,10000] = h @ logW^T + b (champion version) ----------
__global__ __launch_bounds__(256) void logits_gemm(const float* __restrict__ lb,
                                                   float* __restrict__ out) {
    __shared__ __align__(16) __nv_bfloat16 As[64][72];
    __shared__ __align__(16) __nv_bfloat16 Bs[128][72];
    int bm = blockIdx.y, bn = blockIdx.x;
    int tid = threadIdx.x, lane = tid & 31, warp = tid >> 5;
    int arow = tid >> 3, acg = tid & 7;
    const uint4* a0p = (const uint4*)(g_h + (bm * 64 + arow) * NH + acg * 8);
    const uint4* a1p = (const uint4*)(g_h + (bm * 64 + arow + 32) * NH + acg * 8);
    const uint4* bp[4]; bool bv[4];
#pragma unroll
    for (int i = 0; i < 4; i++) {
        int ng = bn * 128 + arow + i * 32;
        bv[i] = ng < NV;
        bp[i] = (const uint4*)(g_logW + (size_t)(bv[i] ? ng : 0) * NH + acg * 8);
    }
    uint4 z4 = make_uint4(0, 0, 0, 0);
    uint4 ra0 = a0p[0], ra1 = a1p[0], rb[4];
#pragma unroll
    for (int i = 0; i < 4; i++) rb[i] = bv[i] ? bp[i][0] : z4;
    int wm = warp >> 2, wn = warp & 3;
    uint32_t ab0 = smem_u32(&As[wm * 32 + (lane & 15)][(lane >> 4) * 8]);
    uint32_t ab1 = ab0 + 16 * 72 * 2;
    uint32_t bb0 = smem_u32(&Bs[wn * 32 + (lane & 15)][(lane >> 4) * 8]);
    uint32_t bb1 = bb0 + 16 * 72 * 2;
    float acc[2][2][2][4] = {};
#pragma unroll 1
    for (int kk = 0; kk < 8; kk++) {
        *(uint4*)&As[arow][acg * 8] = ra0;
        *(uint4*)&As[arow + 32][acg * 8] = ra1;
#pragma unroll
        for (int i = 0; i < 4; i++) *(uint4*)&Bs[arow + i * 32][acg * 8] = rb[i];
        __syncthreads();
        if (kk < 7) {
            ra0 = a0p[(kk + 1) * 8]; ra1 = a1p[(kk + 1) * 8];
#pragma unroll
            for (int i = 0; i < 4; i++) rb[i] = bv[i] ? bp[i][(kk + 1) * 8] : z4;
        }
#pragma unroll
        for (int k16 = 0; k16 < 4; k16++) {
            uint32_t a0[4], a1[4], q0[4], q1[4];
            ldm_x4(a0, ab0 + k16 * 32); ldm_x4(a1, ab1 + k16 * 32);
            ldm_x4(q0, bb0 + k16 * 32); ldm_x4(q1, bb1 + k16 * 32);
            uint32_t b00[2] = {q0[0], q0[2]}, b01[2] = {q0[1], q0[3]};
            uint32_t b10[2] = {q1[0], q1[2]}, b11[2] = {q1[1], q1[3]};
            mma16816(acc[0][0][0], a0, b00); mma16816(acc[0][0][1], a0, b01);
            mma16816(acc[1][0][0], a1, b00); mma16816(acc[1][0][1], a1, b01);
            mma16816(acc[0][1][0], a0, b10); mma16816(acc[0][1][1], a0, b11);
            mma16816(acc[1][1][0], a1, b10); mma16816(acc[1][1][1], a1, b11);
        }
        __syncthreads();
    }
    int g = lane >> 2, tg = lane & 3;
#pragma unroll
    for (int mt = 0; mt < 2; mt++) {
        int row = bm * 64 + wm * 32 + mt * 16 + g;
#pragma unroll
        for (int nt = 0; nt < 2; nt++)
#pragma unroll
            for (int s = 0; s < 2; s++) {
                int col = bn * 128 + wn * 32 + nt * 16 + s * 8 + tg * 2;
                if (col < NV) {
                    float2 bbv = *(const float2*)(lb + col);
                    float* q = acc[mt][nt][s];
                    *(float2*)&out[row * NV + col]       = make_float2(q[0] + bbv.x, q[1] + bbv.y);
                    *(float2*)&out[(row + 8) * NV + col] = make_float2(q[2] + bbv.x, q[3] + bbv.y);
                }
            }
    }
}

// ---------- in-place log_softmax, one block per row ----------
__global__ __launch_bounds__(256) void logsoftmax_kernel(float* __restrict__ out) {
    __shared__ __align__(16) float buf[NV];
    __shared__ float red[10];
    float* p = out + (size_t)blockIdx.x * NV;
    int tid = threadIdx.x, lane = tid & 31, wid = tid >> 5;
    const float4* p4 = (const float4*)p;
    float4* b4 = (float4*)buf;
    float mx = -1e30f;
    for (int i = tid; i < NV / 4; i += 256) {
        float4 v = p4[i]; b4[i] = v;
        mx = fmaxf(fmaxf(mx, v.x), fmaxf(v.y, fmaxf(v.z, v.w)));
    }
#pragma unroll
    for (int o = 16; o; o >>= 1) mx = fmaxf(mx, __shfl_xor_sync(~0u, mx, o));
    if (!lane) red[wid] = mx;
    __syncthreads();
    if (tid == 0) {
        float m = red[0];
        for (int wq = 1; wq < 8; wq++) m = fmaxf(m, red[wq]);
        red[8] = m;
    }
    __syncthreads();
    mx = red[8];
    float s = 0.f;
    for (int i = tid; i < NV / 4; i += 256) {
        float4 v = b4[i];
        s += __expf(v.x - mx) + __expf(v.y - mx) + __expf(v.z - mx) + __expf(v.w - mx);
    }
#pragma unroll
    for (int o = 16; o; o >>= 1) s += __shfl_xor_sync(~0u, s, o);
    if (!lane) red[wid] = s;
    __syncthreads();
    if (tid == 0) {
        float tt = 0.f;
        for (int wq = 0; wq < 8; wq++) tt += red[wq];
        red[9] = mx + logf(tt);
    }
    __syncthreads();
    float lse = red[9];
    for (int i = tid; i < NV / 4; i += 256) {
        float4 v = b4[i];
        ((float4*)p)[i] = make_float4(v.x - lse, v.y - lse, v.z - lse, v.w - lse);
    }
}

extern "C" void kernel_launch(void* const* d_in, const int* in_sizes, int n_in,
                              void* d_out, int out_size) {
    const int*   wi    = (const int*)d_in[0];
    const int*   fi    = (const int*)d_in[1];
    const float* feats = (const float*)d_in[2];
    const float* embed = (const float*)d_in[3];
    const float* fcW   = (const float*)d_in[4];
    const float* fcb   = (const float*)d_in[5];
    const float* Wf1   = (const float*)d_in[6];
    const float* bf1   = (const float*)d_in[7];
    const float* Wf2   = (const float*)d_in[8];
    const float* bf2   = (const float*)d_in[9];
    const float* WH    = (const float*)d_in[10];
    const float* bH    = (const float*)d_in[11];
    const float* WI    = (const float*)d_in[12];
    const float* bI    = (const float*)d_in[13];
    const float* logW  = (const float*)d_in[14];
    const float* logb  = (const float*)d_in[15];
    float* out = (float*)d_out;

    init_convert<<<4096, 256>>>(WH, WI, Wf1, Wf2, logW, bH, bf1, bf2);
    att_kernel<<<2048, 256>>>(feats, fcW, fcb);
    attb_mid<<<2048, 256>>>(WI, bI);
    xgather<<<dim3(NT, NB), 128>>>(wi, fi, embed);
    pre_gemm<<<dim3(20, 48), 256>>>();
    for (int w = 0; w < 13; w++) {
        wave_gemm64<<<dim3(20, h_mtile[w]), 256>>>();
        wave_combine<<<128, 128>>>(w, fi);
    }
    logits_gemm<<<dim3(79, 48), 256>>>(logb, out);
    logsoftmax_kernel<<<NB * NT, 256>>>(out);
}